// round 1
// baseline (speedup 1.0000x reference)
#include <cuda_runtime.h>
#include <cuda_bf16.h>
#include <cstdint>

// Problem constants
#define BATCH 4
#define SEQ   2048
#define DMODEL 512
#define NHEAD 8
#define DHEAD 64

// Scratch buffers (allocation-free rule: __device__ globals)
__device__ float g_q[(size_t)BATCH * SEQ * DMODEL];
__device__ float g_k[(size_t)BATCH * SEQ * DMODEL];
__device__ float g_v[(size_t)BATCH * SEQ * DMODEL];
__device__ float g_a[(size_t)BATCH * SEQ * DMODEL];

// ----------------------------------------------------------------------------
// Tiled fp32 GEMM + bias: C[M,512] = A[M,512] @ W[512,512] + b
// BM=128, BN=64, BK=16, 256 threads, 8x4 per-thread tile.
// ----------------------------------------------------------------------------
__global__ void __launch_bounds__(256) gemm_bias_kernel(
    const float* __restrict__ A, const float* __restrict__ W,
    const float* __restrict__ bias, float* __restrict__ C)
{
    __shared__ float As[16][132];   // transposed A tile, padded
    __shared__ float Bs[16][64];

    const int tid = threadIdx.x;
    const int bx = blockIdx.x;      // n tile (0..7)
    const int by = blockIdx.y;      // m tile (0..63)
    const int tx = tid & 15;        // n sub
    const int ty = tid >> 4;        // m sub

    float acc[8][4];
#pragma unroll
    for (int i = 0; i < 8; i++)
#pragma unroll
        for (int j = 0; j < 4; j++) acc[i][j] = 0.f;

    const float* Ab = A + (size_t)by * 128 * 512;
    const float* Wb = W + bx * 64;

    for (int k0 = 0; k0 < 512; k0 += 16) {
        // Load A tile 128x16 (512 float4, 2/thread), store transposed
#pragma unroll
        for (int i = 0; i < 2; i++) {
            int f = tid + 256 * i;
            int r = f >> 2, c4 = f & 3;
            float4 v = *(const float4*)(Ab + (size_t)r * 512 + k0 + c4 * 4);
            As[c4 * 4 + 0][r] = v.x;
            As[c4 * 4 + 1][r] = v.y;
            As[c4 * 4 + 2][r] = v.z;
            As[c4 * 4 + 3][r] = v.w;
        }
        // Load W tile 16x64 (256 float4, 1/thread)
        {
            int r = tid >> 4, c4 = tid & 15;
            float4 v = *(const float4*)(Wb + (size_t)(k0 + r) * 512 + c4 * 4);
            *(float4*)(&Bs[r][c4 * 4]) = v;
        }
        __syncthreads();

#pragma unroll
        for (int kk = 0; kk < 16; kk++) {
            float4 a0 = *(float4*)&As[kk][ty * 8];
            float4 a1 = *(float4*)&As[kk][ty * 8 + 4];
            float4 b0 = *(float4*)&Bs[kk][tx * 4];
            float a[8] = {a0.x, a0.y, a0.z, a0.w, a1.x, a1.y, a1.z, a1.w};
            float b[4] = {b0.x, b0.y, b0.z, b0.w};
#pragma unroll
            for (int i = 0; i < 8; i++)
#pragma unroll
                for (int j = 0; j < 4; j++)
                    acc[i][j] += a[i] * b[j];
        }
        __syncthreads();
    }

    // Epilogue with bias
    float4 bv = *(const float4*)(bias + bx * 64 + tx * 4);
#pragma unroll
    for (int i = 0; i < 8; i++) {
        int m = by * 128 + ty * 8 + i;
        float4 o;
        o.x = acc[i][0] + bv.x;
        o.y = acc[i][1] + bv.y;
        o.z = acc[i][2] + bv.z;
        o.w = acc[i][3] + bv.w;
        *(float4*)(C + (size_t)m * 512 + bx * 64 + tx * 4) = o;
    }
}

// ----------------------------------------------------------------------------
// Fused attention:
//  grid = (SEQ/32, BATCH*NHEAD), 256 threads (8 warps), warp owns 4 q rows.
//  Pass A: scores tile-by-tile from smem K, write RAW scores into the weights
//          output buffer (scratch), maintain online row max/sum.
//  Pass B: re-read raw scores, normalize -> write final weights, accumulate
//          P @ V with V tiles in smem (w broadcast via shfl).
// ----------------------------------------------------------------------------
__global__ void __launch_bounds__(256) attn_kernel(
    const float* __restrict__ mask, float* __restrict__ wts)
{
    const int qtile = blockIdx.x;           // 0..63
    const int bh    = blockIdx.y;           // 0..31
    const int b = bh >> 3, h = bh & 7;
    const int tid = threadIdx.x;
    const int warp = tid >> 5, lane = tid & 31;

    __shared__ float qs[32][DHEAD];         // q tile (broadcast reads)
    __shared__ float kv[64][68];            // K tile (pass A) / V tile (pass B)

    // ---- load Q tile: 32 rows x 64 (512 float4, 2/thread) ----
    const float* qbase = g_q + ((size_t)(b * SEQ + qtile * 32)) * DMODEL + h * DHEAD;
#pragma unroll
    for (int i = 0; i < 2; i++) {
        int f = tid + 256 * i;
        int r = f >> 4, c4 = f & 15;
        float4 v = *(const float4*)(qbase + (size_t)r * DMODEL + c4 * 4);
        *(float4*)(&qs[r][c4 * 4]) = v;
    }

    float m[4], l[4];
#pragma unroll
    for (int i = 0; i < 4; i++) { m[i] = -1e30f; l[i] = 0.f; }

    float* wrow = wts + ((size_t)bh * SEQ + qtile * 32 + warp * 4) * SEQ;
    const float* kbase = g_k + (size_t)b * SEQ * DMODEL + h * DHEAD;
    const float* vbase = g_v + (size_t)b * SEQ * DMODEL + h * DHEAD;
    const float* mbase = mask + (size_t)b * SEQ;

    // ================= Pass A: scores + online softmax stats =================
    for (int kt = 0; kt < SEQ / 64; ++kt) {
        __syncthreads();
        {   // load K tile 64x64 (1024 float4, 4/thread)
            const float* src = kbase + (size_t)kt * 64 * DMODEL;
#pragma unroll
            for (int i = 0; i < 4; i++) {
                int f = tid + 256 * i;
                int r = f >> 4, c4 = f & 15;
                float4 v = *(const float4*)(src + (size_t)r * DMODEL + c4 * 4);
                *(float4*)(&kv[r][c4 * 4]) = v;
            }
        }
        __syncthreads();

        float mk0 = mbase[kt * 64 + lane] * -1e9f;
        float mk1 = mbase[kt * 64 + 32 + lane] * -1e9f;

        float acc[4][2];
#pragma unroll
        for (int qr = 0; qr < 4; qr++) { acc[qr][0] = 0.f; acc[qr][1] = 0.f; }

#pragma unroll
        for (int d0 = 0; d0 < 64; d0 += 8) {
            float4 k0a = *(float4*)&kv[lane][d0];
            float4 k0b = *(float4*)&kv[lane][d0 + 4];
            float4 k1a = *(float4*)&kv[lane + 32][d0];
            float4 k1b = *(float4*)&kv[lane + 32][d0 + 4];
#pragma unroll
            for (int qr = 0; qr < 4; qr++) {
                float4 qa = *(float4*)&qs[warp * 4 + qr][d0];
                float4 qb = *(float4*)&qs[warp * 4 + qr][d0 + 4];
                acc[qr][0] += qa.x * k0a.x + qa.y * k0a.y + qa.z * k0a.z + qa.w * k0a.w
                            + qb.x * k0b.x + qb.y * k0b.y + qb.z * k0b.z + qb.w * k0b.w;
                acc[qr][1] += qa.x * k1a.x + qa.y * k1a.y + qa.z * k1a.z + qa.w * k1a.w
                            + qb.x * k1b.x + qb.y * k1b.y + qb.z * k1b.z + qb.w * k1b.w;
            }
        }

#pragma unroll
        for (int qr = 0; qr < 4; qr++) {
            float s0 = acc[qr][0] * 0.125f + mk0;
            float s1 = acc[qr][1] * 0.125f + mk1;
            // raw scores -> weights buffer (scratch; pass B normalizes in place)
            wrow[(size_t)qr * SEQ + kt * 64 + lane]      = s0;
            wrow[(size_t)qr * SEQ + kt * 64 + 32 + lane] = s1;
            float tm = fmaxf(s0, s1);
#pragma unroll
            for (int off = 16; off; off >>= 1)
                tm = fmaxf(tm, __shfl_xor_sync(0xffffffffu, tm, off));
            float nm = fmaxf(m[qr], tm);
            float e = __expf(s0 - nm) + __expf(s1 - nm);
#pragma unroll
            for (int off = 16; off; off >>= 1)
                e += __shfl_xor_sync(0xffffffffu, e, off);
            l[qr] = l[qr] * __expf(m[qr] - nm) + e;
            m[qr] = nm;
        }
    }

    float invl[4];
#pragma unroll
    for (int qr = 0; qr < 4; qr++) invl[qr] = 1.f / l[qr];

    // ================= Pass B: normalize weights + P@V =================
    float o[4][2];
#pragma unroll
    for (int qr = 0; qr < 4; qr++) { o[qr][0] = 0.f; o[qr][1] = 0.f; }

    for (int kt = 0; kt < SEQ / 64; ++kt) {
        __syncthreads();
        {   // load V tile 64x64
            const float* src = vbase + (size_t)kt * 64 * DMODEL;
#pragma unroll
            for (int i = 0; i < 4; i++) {
                int f = tid + 256 * i;
                int r = f >> 4, c4 = f & 15;
                float4 v = *(const float4*)(src + (size_t)r * DMODEL + c4 * 4);
                *(float4*)(&kv[r][c4 * 4]) = v;
            }
        }
        __syncthreads();

        float w[4][2];
#pragma unroll
        for (int qr = 0; qr < 4; qr++) {
#pragma unroll
            for (int jj = 0; jj < 2; jj++) {
                size_t idx = (size_t)qr * SEQ + kt * 64 + jj * 32 + lane;
                float s = wrow[idx];
                float wv = __expf(s - m[qr]) * invl[qr];
                wrow[idx] = wv;      // final normalized weight
                w[qr][jj] = wv;
            }
        }

        // o[qr][d] += sum_kc w[qr][kc] * v[kc][d];  lane owns d = {lane, lane+32}
#pragma unroll
        for (int jj = 0; jj < 2; jj++) {
#pragma unroll 8
            for (int src = 0; src < 32; ++src) {
                int kc = jj * 32 + src;
                float va = kv[kc][lane];
                float vb = kv[kc][lane + 32];
#pragma unroll
                for (int qr = 0; qr < 4; qr++) {
                    float wv = __shfl_sync(0xffffffffu, w[qr][jj], src);
                    o[qr][0] += wv * va;
                    o[qr][1] += wv * vb;
                }
            }
        }
    }

    // write attn output (merged-heads layout [b, s, h*64+d])
    float* abase = g_a + ((size_t)(b * SEQ + qtile * 32 + warp * 4)) * DMODEL + h * DHEAD;
#pragma unroll
    for (int qr = 0; qr < 4; qr++) {
        abase[(size_t)qr * DMODEL + lane]      = o[qr][0];
        abase[(size_t)qr * DMODEL + 32 + lane] = o[qr][1];
    }
}

// ----------------------------------------------------------------------------
extern "C" void kernel_launch(void* const* d_in, const int* in_sizes, int n_in,
                              void* d_out, int out_size)
{
    const float* Q    = (const float*)d_in[0];
    const float* K    = (const float*)d_in[1];
    const float* V    = (const float*)d_in[2];
    const float* mask = (const float*)d_in[3];
    const float* Wq_w = (const float*)d_in[4];
    const float* Wq_b = (const float*)d_in[5];
    const float* Wk_w = (const float*)d_in[6];
    const float* Wk_b = (const float*)d_in[7];
    const float* Wv_w = (const float*)d_in[8];
    const float* Wv_b = (const float*)d_in[9];
    const float* Wo_w = (const float*)d_in[10];
    const float* Wo_b = (const float*)d_in[11];

    float* out = (float*)d_out;                                  // [B,S,DM]
    float* wts = out + (size_t)BATCH * SEQ * DMODEL;             // [B,H,S,S]

    float *qb, *kb, *vb, *ab;
    cudaGetSymbolAddress((void**)&qb, g_q);
    cudaGetSymbolAddress((void**)&kb, g_k);
    cudaGetSymbolAddress((void**)&vb, g_v);
    cudaGetSymbolAddress((void**)&ab, g_a);

    dim3 gg(512 / 64, (BATCH * SEQ) / 128);   // (8, 64)
    gemm_bias_kernel<<<gg, 256>>>(Q, Wq_w, Wq_b, qb);
    gemm_bias_kernel<<<gg, 256>>>(K, Wk_w, Wk_b, kb);
    gemm_bias_kernel<<<gg, 256>>>(V, Wv_w, Wv_b, vb);

    attn_kernel<<<dim3(SEQ / 32, BATCH * NHEAD), 256>>>(mask, wts);

    gemm_bias_kernel<<<gg, 256>>>(ab, Wo_w, Wo_b, out);
}

// round 2
// speedup vs baseline: 2.2629x; 2.2629x over previous
#include <cuda_runtime.h>
#include <cuda_bf16.h>
#include <cstdint>

#define BATCH 4
#define SEQ   2048
#define DMODEL 512
#define NHEAD 8
#define DHEAD 64

// Scratch (allocation-free rule: __device__ globals)
__device__ float g_q[(size_t)BATCH * SEQ * DMODEL];
__device__ float g_k[(size_t)BATCH * SEQ * DMODEL];
__device__ float g_v[(size_t)BATCH * SEQ * DMODEL];
__device__ float g_a[(size_t)BATCH * SEQ * DMODEL];

__device__ __forceinline__ float to_tf32(float x) {
    asm("cvt.rna.tf32.f32 %0, %0;" : "+f"(x));
    return x;
}
__device__ __forceinline__ unsigned f2u(float x) { return __float_as_uint(x); }

__device__ __forceinline__ void mma_tf32(float c[4],
    unsigned a0, unsigned a1, unsigned a2, unsigned a3,
    unsigned b0, unsigned b1)
{
    asm volatile(
        "mma.sync.aligned.m16n8k8.row.col.f32.tf32.tf32.f32 "
        "{%0,%1,%2,%3}, {%4,%5,%6,%7}, {%8,%9}, {%0,%1,%2,%3};\n"
        : "+f"(c[0]), "+f"(c[1]), "+f"(c[2]), "+f"(c[3])
        : "r"(a0), "r"(a1), "r"(a2), "r"(a3), "r"(b0), "r"(b1));
}

// ----------------------------------------------------------------------------
// tf32 GEMM + bias: C[M,512] = A[M,512] @ W[512,512] + b
// BM=128, BN=64, BK=16, 256 threads (8 warps: 4m x 2n), warp tile 32x32.
// ----------------------------------------------------------------------------
__global__ void __launch_bounds__(256) gemm_tf32_kernel(
    const float* __restrict__ A, const float* __restrict__ W,
    const float* __restrict__ bias, float* __restrict__ C)
{
    __shared__ float As[128][20];   // m-major, stride 20
    __shared__ float Bs[16][72];    // k-major, stride 72

    const int tid = threadIdx.x;
    const int lane = tid & 31, warp = tid >> 5;
    const int mw = (warp >> 1) * 32;   // warp m offset (0,32,64,96)
    const int nw = (warp & 1) * 32;    // warp n offset (0,32)
    const int r = lane >> 2, c = lane & 3;

    float acc[2][4][4];
#pragma unroll
    for (int i = 0; i < 2; i++)
#pragma unroll
        for (int j = 0; j < 4; j++)
#pragma unroll
            for (int k = 0; k < 4; k++) acc[i][j][k] = 0.f;

    const float* Ab = A + (size_t)blockIdx.y * 128 * 512;
    const float* Wb = W + blockIdx.x * 64;

    for (int k0 = 0; k0 < 512; k0 += 16) {
        // A tile 128x16 (512 float4, 2/thread)
#pragma unroll
        for (int i = 0; i < 2; i++) {
            int f = tid + 256 * i;
            int row = f >> 2, c4 = f & 3;
            float4 v = *(const float4*)(Ab + (size_t)row * 512 + k0 + c4 * 4);
            v.x = to_tf32(v.x); v.y = to_tf32(v.y);
            v.z = to_tf32(v.z); v.w = to_tf32(v.w);
            *(float4*)&As[row][c4 * 4] = v;
        }
        // W tile 16x64 (256 float4, 1/thread)
        {
            int row = tid >> 4, c4 = tid & 15;
            float4 v = *(const float4*)(Wb + (size_t)(k0 + row) * 512 + c4 * 4);
            v.x = to_tf32(v.x); v.y = to_tf32(v.y);
            v.z = to_tf32(v.z); v.w = to_tf32(v.w);
            *(float4*)&Bs[row][c4 * 4] = v;
        }
        __syncthreads();

#pragma unroll
        for (int ks = 0; ks < 16; ks += 8) {
            unsigned a[2][4];
#pragma unroll
            for (int mt = 0; mt < 2; mt++) {
                a[mt][0] = f2u(As[mw + mt * 16 + r][ks + c]);
                a[mt][1] = f2u(As[mw + mt * 16 + r + 8][ks + c]);
                a[mt][2] = f2u(As[mw + mt * 16 + r][ks + c + 4]);
                a[mt][3] = f2u(As[mw + mt * 16 + r + 8][ks + c + 4]);
            }
#pragma unroll
            for (int nt = 0; nt < 4; nt++) {
                unsigned b0 = f2u(Bs[ks + c][nw + nt * 8 + r]);
                unsigned b1 = f2u(Bs[ks + c + 4][nw + nt * 8 + r]);
                mma_tf32(acc[0][nt], a[0][0], a[0][1], a[0][2], a[0][3], b0, b1);
                mma_tf32(acc[1][nt], a[1][0], a[1][1], a[1][2], a[1][3], b0, b1);
            }
        }
        __syncthreads();
    }

#pragma unroll
    for (int mt = 0; mt < 2; mt++)
#pragma unroll
    for (int nt = 0; nt < 4; nt++) {
        int col = blockIdx.x * 64 + nw + nt * 8 + 2 * c;
        float bx = bias[col], by = bias[col + 1];
        size_t row0 = blockIdx.y * 128 + mw + mt * 16 + r;
        float2 v0 = make_float2(acc[mt][nt][0] + bx, acc[mt][nt][1] + by);
        float2 v1 = make_float2(acc[mt][nt][2] + bx, acc[mt][nt][3] + by);
        *(float2*)(C + row0 * 512 + col) = v0;
        *(float2*)(C + (row0 + 8) * 512 + col) = v1;
    }
}

// ----------------------------------------------------------------------------
// Tensor-core flash attention (two-pass, recompute).
// Block: 64 q rows for one (b,h). 256 threads, 8 warps (4m x 2n).
// Warp score tile: 16x32 (1 m-tile x 4 n-tiles of m16n8k8).
// ----------------------------------------------------------------------------
#define ASTR 68

__global__ void __launch_bounds__(256) attn_tc_kernel(
    const float* __restrict__ mask, float* __restrict__ wts)
{
    extern __shared__ float sh[];
    float* Qs = sh;                    // [64][68]
    float* Ks = sh + 64 * ASTR;        // [64][68]
    float* Vs = sh + 2 * 64 * ASTR;    // [64][68]
    float* Ps = sh + 3 * 64 * ASTR;    // [64][68]
    float* mkS  = sh + 4 * 64 * ASTR;  // [64]
    float* mS   = mkS + 64;            // [64]
    float* lS   = mS + 64;             // [64]  (becomes invl for pass B)
    float* tmax = lS + 64;             // [64][2]
    float* tsum = tmax + 128;          // [64][2]

    const int tid = threadIdx.x;
    const int lane = tid & 31, warp = tid >> 5;
    const int mw = (warp >> 1) * 16;   // 0,16,32,48
    const int nwi = warp & 1;
    const int nw = nwi * 32;
    const int r = lane >> 2, c = lane & 3;

    const int qt = blockIdx.x;         // 0..31
    const int bh = blockIdx.y;         // 0..31
    const int b = bh >> 3, h = bh & 7;
    const int q0 = qt * 64;

    const float* qbase = g_q + ((size_t)(b * SEQ + q0)) * DMODEL + h * DHEAD;
    const float* kbase = g_k + (size_t)b * SEQ * DMODEL + h * DHEAD;
    const float* vbase = g_v + (size_t)b * SEQ * DMODEL + h * DHEAD;
    const float* mbase = mask + (size_t)b * SEQ;

    // Q tile 64x64 (tf32-rounded)
#pragma unroll
    for (int i = 0; i < 4; i++) {
        int f = tid + 256 * i;
        int row = f >> 4, c4 = f & 15;
        float4 v = *(const float4*)(qbase + (size_t)row * DMODEL + c4 * 4);
        v.x = to_tf32(v.x); v.y = to_tf32(v.y);
        v.z = to_tf32(v.z); v.w = to_tf32(v.w);
        *(float4*)&Qs[row * ASTR + c4 * 4] = v;
    }
    if (tid < 64) { mS[tid] = -1e30f; lS[tid] = 0.f; }

    // ================= Pass A: stats only =================
    for (int kt = 0; kt < SEQ / 64; ++kt) {
        const float* src = kbase + (size_t)kt * 64 * DMODEL;
#pragma unroll
        for (int i = 0; i < 4; i++) {
            int f = tid + 256 * i;
            int row = f >> 4, c4 = f & 15;
            float4 v = *(const float4*)(src + (size_t)row * DMODEL + c4 * 4);
            v.x = to_tf32(v.x); v.y = to_tf32(v.y);
            v.z = to_tf32(v.z); v.w = to_tf32(v.w);
            *(float4*)&Ks[row * ASTR + c4 * 4] = v;
        }
        if (tid < 16) {
            float4 mv = *(const float4*)(mbase + kt * 64 + tid * 4);
            mkS[tid * 4 + 0] = mv.x * -1e9f;
            mkS[tid * 4 + 1] = mv.y * -1e9f;
            mkS[tid * 4 + 2] = mv.z * -1e9f;
            mkS[tid * 4 + 3] = mv.w * -1e9f;
        }
        __syncthreads();

        float sf[4][4];
#pragma unroll
        for (int nt = 0; nt < 4; nt++)
#pragma unroll
            for (int j = 0; j < 4; j++) sf[nt][j] = 0.f;

#pragma unroll
        for (int ks = 0; ks < 64; ks += 8) {
            unsigned a0 = f2u(Qs[(mw + r) * ASTR + ks + c]);
            unsigned a1 = f2u(Qs[(mw + r + 8) * ASTR + ks + c]);
            unsigned a2 = f2u(Qs[(mw + r) * ASTR + ks + c + 4]);
            unsigned a3 = f2u(Qs[(mw + r + 8) * ASTR + ks + c + 4]);
#pragma unroll
            for (int nt = 0; nt < 4; nt++) {
                unsigned b0 = f2u(Ks[(nw + nt * 8 + r) * ASTR + ks + c]);
                unsigned b1 = f2u(Ks[(nw + nt * 8 + r) * ASTR + ks + c + 4]);
                mma_tf32(sf[nt], a0, a1, a2, a3, b0, b1);
            }
        }

        float mx0 = -1e30f, mx1 = -1e30f;
#pragma unroll
        for (int nt = 0; nt < 4; nt++) {
            int col = nw + nt * 8 + 2 * c;
            float m0v = mkS[col], m1v = mkS[col + 1];
            sf[nt][0] = sf[nt][0] * 0.125f + m0v;
            sf[nt][1] = sf[nt][1] * 0.125f + m1v;
            sf[nt][2] = sf[nt][2] * 0.125f + m0v;
            sf[nt][3] = sf[nt][3] * 0.125f + m1v;
            mx0 = fmaxf(mx0, fmaxf(sf[nt][0], sf[nt][1]));
            mx1 = fmaxf(mx1, fmaxf(sf[nt][2], sf[nt][3]));
        }
        mx0 = fmaxf(mx0, __shfl_xor_sync(0xffffffffu, mx0, 1));
        mx0 = fmaxf(mx0, __shfl_xor_sync(0xffffffffu, mx0, 2));
        mx1 = fmaxf(mx1, __shfl_xor_sync(0xffffffffu, mx1, 1));
        mx1 = fmaxf(mx1, __shfl_xor_sync(0xffffffffu, mx1, 2));
        if (c == 0) {
            tmax[(mw + r) * 2 + nwi] = mx0;
            tmax[(mw + r + 8) * 2 + nwi] = mx1;
        }
        __syncthreads();
        if (tid < 64) {
            float nm = fmaxf(mS[tid], fmaxf(tmax[tid * 2], tmax[tid * 2 + 1]));
            lS[tid] *= __expf(mS[tid] - nm);
            mS[tid] = nm;
        }
        __syncthreads();

        float rm0 = mS[mw + r], rm1 = mS[mw + r + 8];
        float s0 = 0.f, s1 = 0.f;
#pragma unroll
        for (int nt = 0; nt < 4; nt++) {
            s0 += __expf(sf[nt][0] - rm0) + __expf(sf[nt][1] - rm0);
            s1 += __expf(sf[nt][2] - rm1) + __expf(sf[nt][3] - rm1);
        }
        s0 += __shfl_xor_sync(0xffffffffu, s0, 1);
        s0 += __shfl_xor_sync(0xffffffffu, s0, 2);
        s1 += __shfl_xor_sync(0xffffffffu, s1, 1);
        s1 += __shfl_xor_sync(0xffffffffu, s1, 2);
        if (c == 0) {
            tsum[(mw + r) * 2 + nwi] = s0;
            tsum[(mw + r + 8) * 2 + nwi] = s1;
        }
        __syncthreads();
        if (tid < 64) lS[tid] += tsum[tid * 2] + tsum[tid * 2 + 1];
        // next-iteration syncthreads (after tile load) orders the rest
    }

    __syncthreads();
    if (tid < 64) lS[tid] = 1.f / lS[tid];   // lS now holds invl

    // ================= Pass B: weights + PV =================
    float of[4][4];
#pragma unroll
    for (int nt = 0; nt < 4; nt++)
#pragma unroll
        for (int j = 0; j < 4; j++) of[nt][j] = 0.f;

    float* wbase = wts + ((size_t)bh * SEQ + q0) * SEQ;

    for (int kt = 0; kt < SEQ / 64; ++kt) {
        const float* ksrc = kbase + (size_t)kt * 64 * DMODEL;
        const float* vsrc = vbase + (size_t)kt * 64 * DMODEL;
#pragma unroll
        for (int i = 0; i < 4; i++) {
            int f = tid + 256 * i;
            int row = f >> 4, c4 = f & 15;
            float4 v = *(const float4*)(ksrc + (size_t)row * DMODEL + c4 * 4);
            v.x = to_tf32(v.x); v.y = to_tf32(v.y);
            v.z = to_tf32(v.z); v.w = to_tf32(v.w);
            *(float4*)&Ks[row * ASTR + c4 * 4] = v;
            float4 w = *(const float4*)(vsrc + (size_t)row * DMODEL + c4 * 4);
            w.x = to_tf32(w.x); w.y = to_tf32(w.y);
            w.z = to_tf32(w.z); w.w = to_tf32(w.w);
            *(float4*)&Vs[row * ASTR + c4 * 4] = w;
        }
        if (tid < 16) {
            float4 mv = *(const float4*)(mbase + kt * 64 + tid * 4);
            mkS[tid * 4 + 0] = mv.x * -1e9f;
            mkS[tid * 4 + 1] = mv.y * -1e9f;
            mkS[tid * 4 + 2] = mv.z * -1e9f;
            mkS[tid * 4 + 3] = mv.w * -1e9f;
        }
        __syncthreads();

        // recompute S
        float sf[4][4];
#pragma unroll
        for (int nt = 0; nt < 4; nt++)
#pragma unroll
            for (int j = 0; j < 4; j++) sf[nt][j] = 0.f;
#pragma unroll
        for (int ks = 0; ks < 64; ks += 8) {
            unsigned a0 = f2u(Qs[(mw + r) * ASTR + ks + c]);
            unsigned a1 = f2u(Qs[(mw + r + 8) * ASTR + ks + c]);
            unsigned a2 = f2u(Qs[(mw + r) * ASTR + ks + c + 4]);
            unsigned a3 = f2u(Qs[(mw + r + 8) * ASTR + ks + c + 4]);
#pragma unroll
            for (int nt = 0; nt < 4; nt++) {
                unsigned b0 = f2u(Ks[(nw + nt * 8 + r) * ASTR + ks + c]);
                unsigned b1 = f2u(Ks[(nw + nt * 8 + r) * ASTR + ks + c + 4]);
                mma_tf32(sf[nt], a0, a1, a2, a3, b0, b1);
            }
        }

        float rm0 = mS[mw + r], rm1 = mS[mw + r + 8];
        float il0 = lS[mw + r], il1 = lS[mw + r + 8];
#pragma unroll
        for (int nt = 0; nt < 4; nt++) {
            int col = nw + nt * 8 + 2 * c;
            float m0v = mkS[col], m1v = mkS[col + 1];
            float p0 = __expf(sf[nt][0] * 0.125f + m0v - rm0) * il0;
            float p1 = __expf(sf[nt][1] * 0.125f + m1v - rm0) * il0;
            float p2 = __expf(sf[nt][2] * 0.125f + m0v - rm1) * il1;
            float p3 = __expf(sf[nt][3] * 0.125f + m1v - rm1) * il1;
            // full-precision weights to global
            float* wp = wbase + (size_t)(mw + r) * SEQ + kt * 64 + col;
            *(float2*)wp = make_float2(p0, p1);
            *(float2*)(wp + 8 * SEQ) = make_float2(p2, p3);
            // tf32-rounded P to smem for PV mma
            Ps[(mw + r) * ASTR + col]       = to_tf32(p0);
            Ps[(mw + r) * ASTR + col + 1]   = to_tf32(p1);
            Ps[(mw + r + 8) * ASTR + col]     = to_tf32(p2);
            Ps[(mw + r + 8) * ASTR + col + 1] = to_tf32(p3);
        }
        __syncthreads();

        // O += P @ V
#pragma unroll
        for (int ks = 0; ks < 64; ks += 8) {
            unsigned a0 = f2u(Ps[(mw + r) * ASTR + ks + c]);
            unsigned a1 = f2u(Ps[(mw + r + 8) * ASTR + ks + c]);
            unsigned a2 = f2u(Ps[(mw + r) * ASTR + ks + c + 4]);
            unsigned a3 = f2u(Ps[(mw + r + 8) * ASTR + ks + c + 4]);
#pragma unroll
            for (int nt = 0; nt < 4; nt++) {
                unsigned b0 = f2u(Vs[(ks + c) * ASTR + nw + nt * 8 + r]);
                unsigned b1 = f2u(Vs[(ks + c + 4) * ASTR + nw + nt * 8 + r]);
                mma_tf32(of[nt], a0, a1, a2, a3, b0, b1);
            }
        }
        __syncthreads();
    }

    // write O (merged-heads layout)
    float* abase = g_a + ((size_t)(b * SEQ + q0)) * DMODEL + h * DHEAD;
#pragma unroll
    for (int nt = 0; nt < 4; nt++) {
        int col = nw + nt * 8 + 2 * c;
        *(float2*)(abase + (size_t)(mw + r) * DMODEL + col) =
            make_float2(of[nt][0], of[nt][1]);
        *(float2*)(abase + (size_t)(mw + r + 8) * DMODEL + col) =
            make_float2(of[nt][2], of[nt][3]);
    }
}

// ----------------------------------------------------------------------------
extern "C" void kernel_launch(void* const* d_in, const int* in_sizes, int n_in,
                              void* d_out, int out_size)
{
    const float* Q    = (const float*)d_in[0];
    const float* K    = (const float*)d_in[1];
    const float* V    = (const float*)d_in[2];
    const float* mask = (const float*)d_in[3];
    const float* Wq_w = (const float*)d_in[4];
    const float* Wq_b = (const float*)d_in[5];
    const float* Wk_w = (const float*)d_in[6];
    const float* Wk_b = (const float*)d_in[7];
    const float* Wv_w = (const float*)d_in[8];
    const float* Wv_b = (const float*)d_in[9];
    const float* Wo_w = (const float*)d_in[10];
    const float* Wo_b = (const float*)d_in[11];

    float* out = (float*)d_out;
    float* wts = out + (size_t)BATCH * SEQ * DMODEL;

    float *qb, *kb, *vb, *ab;
    cudaGetSymbolAddress((void**)&qb, g_q);
    cudaGetSymbolAddress((void**)&kb, g_k);
    cudaGetSymbolAddress((void**)&vb, g_v);
    cudaGetSymbolAddress((void**)&ab, g_a);

    const int attn_smem = (4 * 64 * ASTR + 64 * 3 + 256) * 4;
    cudaFuncSetAttribute(attn_tc_kernel,
                         cudaFuncAttributeMaxDynamicSharedMemorySize, attn_smem);

    dim3 gg(512 / 64, (BATCH * SEQ) / 128);
    gemm_tf32_kernel<<<gg, 256>>>(Q, Wq_w, Wq_b, qb);
    gemm_tf32_kernel<<<gg, 256>>>(K, Wk_w, Wk_b, kb);
    gemm_tf32_kernel<<<gg, 256>>>(V, Wv_w, Wv_b, vb);

    attn_tc_kernel<<<dim3(SEQ / 64, BATCH * NHEAD), 256, attn_smem>>>(mask, wts);

    gemm_tf32_kernel<<<gg, 256>>>(ab, Wo_w, Wo_b, out);
}

// round 3
// speedup vs baseline: 2.3534x; 1.0400x over previous
#include <cuda_runtime.h>
#include <cstdint>

#define BATCH 4
#define SEQ   2048
#define DMODEL 512
#define NHEAD 8
#define DHEAD 64
#define ASTR 68          // attention smem row stride (floats)
#define NKT  (SEQ / 64)  // 32 k-tiles

// Scratch (allocation-free rule: __device__ globals)
__device__ float g_q[(size_t)BATCH * SEQ * DMODEL];
__device__ float g_k[(size_t)BATCH * SEQ * DMODEL];
__device__ float g_v[(size_t)BATCH * SEQ * DMODEL];
__device__ float g_a[(size_t)BATCH * SEQ * DMODEL];

__device__ __forceinline__ float to_tf32(float x) {
    asm("cvt.rna.tf32.f32 %0, %0;" : "+f"(x));
    return x;
}
__device__ __forceinline__ unsigned f2u(float x) { return __float_as_uint(x); }
__device__ __forceinline__ unsigned s2u(const void* p) {
    return (unsigned)__cvta_generic_to_shared(p);
}

__device__ __forceinline__ void mma_tf32(float c[4], const unsigned a[4],
                                         unsigned b0, unsigned b1)
{
    asm volatile(
        "mma.sync.aligned.m16n8k8.row.col.f32.tf32.tf32.f32 "
        "{%0,%1,%2,%3}, {%4,%5,%6,%7}, {%8,%9}, {%0,%1,%2,%3};\n"
        : "+f"(c[0]), "+f"(c[1]), "+f"(c[2]), "+f"(c[3])
        : "r"(a[0]), "r"(a[1]), "r"(a[2]), "r"(a[3]), "r"(b0), "r"(b1));
}

__device__ __forceinline__ void ldsm4(unsigned r[4], unsigned addr) {
    asm volatile("ldmatrix.sync.aligned.m8n8.x4.shared.b16 {%0,%1,%2,%3}, [%4];"
        : "=r"(r[0]), "=r"(r[1]), "=r"(r[2]), "=r"(r[3]) : "r"(addr));
}

#define CP16(dst, src) \
    asm volatile("cp.async.cg.shared.global [%0], [%1], 16;" :: "r"(dst), "l"(src))
#define CP_COMMIT()  asm volatile("cp.async.commit_group;")
#define CP_WAIT0()   asm volatile("cp.async.wait_group 0;" ::: "memory")

// ----------------------------------------------------------------------------
// tf32 GEMM + bias. C[M,512] = A[M,512] @ W[512,512] + b.
// BM=128, BN=64, BK=16, 8 warps (4m x 2n), warp tile 32x32, ldmatrix frags,
// reg-staged double buffering.
// MODE: 0 = plain fp32 out; 1 = tf32-rounded out; 2 = tf32-rounded * 0.125
// ----------------------------------------------------------------------------
template<int MODE>
__global__ void __launch_bounds__(256) gemm2(
    const float* __restrict__ A, const float* __restrict__ W,
    const float* __restrict__ bias, float* __restrict__ C)
{
    __shared__ float As[2][128 * 20];
    __shared__ float Wt[2][64 * 20];

    const int tid = threadIdx.x;
    const int lane = tid & 31, warp = tid >> 5;
    const int mw = (warp >> 1) * 32;
    const int nw = (warp & 1) * 32;
    const int r = lane >> 2, c = lane & 3;

    float acc[2][4][4];
#pragma unroll
    for (int i = 0; i < 2; i++)
#pragma unroll
        for (int j = 0; j < 4; j++)
#pragma unroll
            for (int k = 0; k < 4; k++) acc[i][j][k] = 0.f;

    const float* Ab = A + (size_t)blockIdx.y * 128 * 512;
    const float* Wb = W + blockIdx.x * 64;

    const int arow = tid >> 2, ac4 = tid & 3;   // A rows arow, arow+64
    const int wrow = tid >> 4, wc4 = tid & 15;  // W row(k), n quad

    // fragment smem addresses (byte)
    unsigned uA0 = s2u(&As[0][0]) +
        (((mw + (lane & 15)) * 20) + ((lane >> 4) << 2)) * 4;
    unsigned uA1 = uA0 + 16 * 20 * 4;
    unsigned uB0 = s2u(&Wt[0][0]) +
        (((nw + (lane & 7) + ((lane >> 4) << 3)) * 20) + (((lane >> 3) & 1) << 2)) * 4;
    unsigned uB1 = uB0 + 16 * 20 * 4;

    float4 aR0, aR1, wR;
    aR0 = *(const float4*)(Ab + (size_t)arow * 512 + ac4 * 4);
    aR1 = *(const float4*)(Ab + (size_t)(arow + 64) * 512 + ac4 * 4);
    wR  = *(const float4*)(Wb + (size_t)wrow * 512 + wc4 * 4);
    {
        float4 v = aR0;
        v.x = to_tf32(v.x); v.y = to_tf32(v.y); v.z = to_tf32(v.z); v.w = to_tf32(v.w);
        *(float4*)&As[0][arow * 20 + ac4 * 4] = v;
        v = aR1;
        v.x = to_tf32(v.x); v.y = to_tf32(v.y); v.z = to_tf32(v.z); v.w = to_tf32(v.w);
        *(float4*)&As[0][(arow + 64) * 20 + ac4 * 4] = v;
        Wt[0][(wc4 * 4 + 0) * 20 + wrow] = to_tf32(wR.x);
        Wt[0][(wc4 * 4 + 1) * 20 + wrow] = to_tf32(wR.y);
        Wt[0][(wc4 * 4 + 2) * 20 + wrow] = to_tf32(wR.z);
        Wt[0][(wc4 * 4 + 3) * 20 + wrow] = to_tf32(wR.w);
    }
    __syncthreads();

    for (int k0 = 0; k0 < 512; k0 += 16) {
        const int cur = (k0 >> 4) & 1;
        const bool nxt = (k0 + 16) < 512;
        if (nxt) {
            aR0 = *(const float4*)(Ab + (size_t)arow * 512 + k0 + 16 + ac4 * 4);
            aR1 = *(const float4*)(Ab + (size_t)(arow + 64) * 512 + k0 + 16 + ac4 * 4);
            wR  = *(const float4*)(Wb + (size_t)(k0 + 16 + wrow) * 512 + wc4 * 4);
        }
#pragma unroll
        for (int ks = 0; ks < 16; ks += 8) {
            unsigned a0[4], a1[4], bF[4];
            ldsm4(a0, uA0 + cur * 10240 + ks * 4);
            ldsm4(a1, uA1 + cur * 10240 + ks * 4);
            ldsm4(bF, uB0 + cur * 5120 + ks * 4);
            mma_tf32(acc[0][0], a0, bF[0], bF[1]);
            mma_tf32(acc[0][1], a0, bF[2], bF[3]);
            mma_tf32(acc[1][0], a1, bF[0], bF[1]);
            mma_tf32(acc[1][1], a1, bF[2], bF[3]);
            ldsm4(bF, uB1 + cur * 5120 + ks * 4);
            mma_tf32(acc[0][2], a0, bF[0], bF[1]);
            mma_tf32(acc[0][3], a0, bF[2], bF[3]);
            mma_tf32(acc[1][2], a1, bF[0], bF[1]);
            mma_tf32(acc[1][3], a1, bF[2], bF[3]);
        }
        if (nxt) {
            const int nb = cur ^ 1;
            float4 v = aR0;
            v.x = to_tf32(v.x); v.y = to_tf32(v.y); v.z = to_tf32(v.z); v.w = to_tf32(v.w);
            *(float4*)&As[nb][arow * 20 + ac4 * 4] = v;
            v = aR1;
            v.x = to_tf32(v.x); v.y = to_tf32(v.y); v.z = to_tf32(v.z); v.w = to_tf32(v.w);
            *(float4*)&As[nb][(arow + 64) * 20 + ac4 * 4] = v;
            Wt[nb][(wc4 * 4 + 0) * 20 + wrow] = to_tf32(wR.x);
            Wt[nb][(wc4 * 4 + 1) * 20 + wrow] = to_tf32(wR.y);
            Wt[nb][(wc4 * 4 + 2) * 20 + wrow] = to_tf32(wR.z);
            Wt[nb][(wc4 * 4 + 3) * 20 + wrow] = to_tf32(wR.w);
        }
        __syncthreads();
    }

#pragma unroll
    for (int mt = 0; mt < 2; mt++)
#pragma unroll
    for (int nt = 0; nt < 4; nt++) {
        int col = blockIdx.x * 64 + nw + nt * 8 + 2 * c;
        float bx = __ldg(bias + col), by = __ldg(bias + col + 1);
        size_t row0 = blockIdx.y * 128 + mw + mt * 16 + r;
        float v0 = acc[mt][nt][0] + bx, v1 = acc[mt][nt][1] + by;
        float v2 = acc[mt][nt][2] + bx, v3 = acc[mt][nt][3] + by;
        if (MODE == 2) { v0 *= 0.125f; v1 *= 0.125f; v2 *= 0.125f; v3 *= 0.125f; }
        if (MODE >= 1) {
            v0 = to_tf32(v0); v1 = to_tf32(v1); v2 = to_tf32(v2); v3 = to_tf32(v3);
        }
        *(float2*)(C + row0 * 512 + col) = make_float2(v0, v1);
        *(float2*)(C + (row0 + 8) * 512 + col) = make_float2(v2, v3);
    }
}

// ----------------------------------------------------------------------------
// Tensor-core flash attention, two-pass recompute, ldmatrix + cp.async.
// Block: 64 q rows, 8 warps (4m x 2n), warp S-tile 16x32.
// Smem (floats): Qs 4352 | Kb 2x4352 | Vb 2x4352 | Ps 4352 | msk 2048 | stats
// ----------------------------------------------------------------------------
#define OFF_K   4352
#define OFF_V   13056
#define OFF_P   21760
#define OFF_MSK 26112
#define OFF_MS  28160
#define OFF_LS  28224
#define OFF_PMX 28288
#define OFF_PSM 28416
#define ATTN_SMEM_FLOATS 28544
#define KBUF_BYTES (4352 * 4)

__global__ void __launch_bounds__(256, 2) attn3(
    const float* __restrict__ mask, float* __restrict__ wts)
{
    extern __shared__ float sh[];
    float* Qs  = sh;
    float* msk = sh + OFF_MSK;
    float* mS  = sh + OFF_MS;
    float* lS  = sh + OFF_LS;
    float* pmx = sh + OFF_PMX;
    float* psm = sh + OFF_PSM;

    const int tid = threadIdx.x;
    const int lane = tid & 31, warp = tid >> 5;
    const int mw = (warp >> 1) * 16;
    const int nwi = warp & 1;
    const int nw = nwi * 32;
    const int r = lane >> 2, c = lane & 3;

    const int qt = blockIdx.x, bh = blockIdx.y;
    const int b = bh >> 3, h = bh & 7;
    const int q0 = qt * 64;

    const float* qg = g_q + ((size_t)(b * SEQ + q0)) * DMODEL + h * DHEAD;
    const float* kg = g_k + (size_t)b * SEQ * DMODEL + h * DHEAD;
    const float* vg = g_v + (size_t)b * SEQ * DMODEL + h * DHEAD;

    const unsigned uQst = s2u(sh);
    const unsigned uKst = s2u(sh + OFF_K);
    const unsigned uVst = s2u(sh + OFF_V);

    // issue Q + K0 copies
#pragma unroll
    for (int i = 0; i < 4; i++) {
        int f = tid + 256 * i;
        int row = f >> 4, c4 = f & 15;
        unsigned so = (unsigned)(row * ASTR + c4 * 4) * 4;
        CP16(uQst + so, qg + (size_t)row * DMODEL + c4 * 4);
        CP16(uKst + so, kg + (size_t)row * DMODEL + c4 * 4);
    }
    CP_COMMIT();
    // mask -> smem (pre-multiplied by -1e9)
#pragma unroll
    for (int j = 0; j < 2; j++) {
        int idx = tid + 256 * j;
        float4 mv = *(const float4*)(mask + (size_t)b * SEQ + idx * 4);
        msk[idx * 4 + 0] = mv.x * -1e9f;
        msk[idx * 4 + 1] = mv.y * -1e9f;
        msk[idx * 4 + 2] = mv.z * -1e9f;
        msk[idx * 4 + 3] = mv.w * -1e9f;
    }
    if (tid < 64) { mS[tid] = -1e30f; lS[tid] = 0.f; }
    CP_WAIT0();
    __syncthreads();

    // fragment base addresses (byte)
    const unsigned fragA_off =
        (((lane & 15)) * ASTR + ((lane >> 4) << 2)) * 4;
    const unsigned uQ = uQst + mw * ASTR * 4 + fragA_off;
    const unsigned uP = s2u(sh + OFF_P) + mw * ASTR * 4 + fragA_off;
    unsigned uK[2];
#pragma unroll
    for (int ntp = 0; ntp < 2; ntp++)
        uK[ntp] = uKst +
            (((nw + ntp * 16 + (lane & 7) + ((lane >> 4) << 3)) * ASTR) +
             (((lane >> 3) & 1) << 2)) * 4;

    // ======================= Pass A: stats =======================
    for (int kt = 0; kt < NKT; ++kt) {
        const int cur = kt & 1;
        if (kt + 1 < NKT) {
            const int nb = (kt + 1) & 1;
            const float* src = kg + (size_t)(kt + 1) * 64 * DMODEL;
#pragma unroll
            for (int i = 0; i < 4; i++) {
                int f = tid + 256 * i;
                int row = f >> 4, c4 = f & 15;
                CP16(uKst + nb * KBUF_BYTES + (unsigned)(row * ASTR + c4 * 4) * 4,
                     src + (size_t)row * DMODEL + c4 * 4);
            }
            CP_COMMIT();
        }

        float sf[4][4];
#pragma unroll
        for (int nt = 0; nt < 4; nt++)
#pragma unroll
            for (int j = 0; j < 4; j++) sf[nt][j] = 0.f;

#pragma unroll
        for (int ks = 0; ks < 64; ks += 8) {
            unsigned a[4], bF[4];
            ldsm4(a, uQ + ks * 4);
            ldsm4(bF, uK[0] + cur * KBUF_BYTES + ks * 4);
            mma_tf32(sf[0], a, bF[0], bF[1]);
            mma_tf32(sf[1], a, bF[2], bF[3]);
            ldsm4(bF, uK[1] + cur * KBUF_BYTES + ks * 4);
            mma_tf32(sf[2], a, bF[0], bF[1]);
            mma_tf32(sf[3], a, bF[2], bF[3]);
        }

        float mx0 = -1e30f, mx1 = -1e30f;
#pragma unroll
        for (int nt = 0; nt < 4; nt++) {
            int col = kt * 64 + nw + nt * 8 + 2 * c;
            float mk0 = msk[col], mk1 = msk[col + 1];
            sf[nt][0] += mk0; sf[nt][1] += mk1;
            sf[nt][2] += mk0; sf[nt][3] += mk1;
            mx0 = fmaxf(mx0, fmaxf(sf[nt][0], sf[nt][1]));
            mx1 = fmaxf(mx1, fmaxf(sf[nt][2], sf[nt][3]));
        }
        mx0 = fmaxf(mx0, __shfl_xor_sync(0xffffffffu, mx0, 1));
        mx0 = fmaxf(mx0, __shfl_xor_sync(0xffffffffu, mx0, 2));
        mx1 = fmaxf(mx1, __shfl_xor_sync(0xffffffffu, mx1, 1));
        mx1 = fmaxf(mx1, __shfl_xor_sync(0xffffffffu, mx1, 2));
        float s0 = 0.f, s1 = 0.f;
#pragma unroll
        for (int nt = 0; nt < 4; nt++) {
            s0 += __expf(sf[nt][0] - mx0) + __expf(sf[nt][1] - mx0);
            s1 += __expf(sf[nt][2] - mx1) + __expf(sf[nt][3] - mx1);
        }
        s0 += __shfl_xor_sync(0xffffffffu, s0, 1);
        s0 += __shfl_xor_sync(0xffffffffu, s0, 2);
        s1 += __shfl_xor_sync(0xffffffffu, s1, 1);
        s1 += __shfl_xor_sync(0xffffffffu, s1, 2);
        if (c == 0) {
            pmx[(mw + r) * 2 + nwi] = mx0;      psm[(mw + r) * 2 + nwi] = s0;
            pmx[(mw + r + 8) * 2 + nwi] = mx1;  psm[(mw + r + 8) * 2 + nwi] = s1;
        }
        __syncthreads();
        if (tid < 64) {
            float ma = pmx[tid * 2], mb = pmx[tid * 2 + 1];
            float nm = fmaxf(mS[tid], fmaxf(ma, mb));
            lS[tid] = lS[tid] * __expf(mS[tid] - nm)
                    + psm[tid * 2] * __expf(ma - nm)
                    + psm[tid * 2 + 1] * __expf(mb - nm);
            mS[tid] = nm;
        }
        CP_WAIT0();
        __syncthreads();
    }

    if (tid < 64) lS[tid] = 1.f / lS[tid];
    __syncthreads();

    const float rm0 = mS[mw + r], rm1 = mS[mw + r + 8];
    const float il0 = lS[mw + r], il1 = lS[mw + r + 8];

    // prologue pass B: K0 + V0
#pragma unroll
    for (int i = 0; i < 4; i++) {
        int f = tid + 256 * i;
        int row = f >> 4, c4 = f & 15;
        unsigned so = (unsigned)(row * ASTR + c4 * 4) * 4;
        CP16(uKst + so, kg + (size_t)row * DMODEL + c4 * 4);
        CP16(uVst + so, vg + (size_t)row * DMODEL + c4 * 4);
    }
    CP_COMMIT();
    CP_WAIT0();
    __syncthreads();

    // ======================= Pass B: weights + PV =======================
    float of[4][4];
#pragma unroll
    for (int nt = 0; nt < 4; nt++)
#pragma unroll
        for (int j = 0; j < 4; j++) of[nt][j] = 0.f;

    float* wb = wts + ((size_t)bh * SEQ + q0) * SEQ;
    float* Ps = sh + OFF_P;

    for (int kt = 0; kt < NKT; ++kt) {
        const int cur = kt & 1;
        if (kt + 1 < NKT) {
            const int nb = (kt + 1) & 1;
            const float* ksrc = kg + (size_t)(kt + 1) * 64 * DMODEL;
            const float* vsrc = vg + (size_t)(kt + 1) * 64 * DMODEL;
#pragma unroll
            for (int i = 0; i < 4; i++) {
                int f = tid + 256 * i;
                int row = f >> 4, c4 = f & 15;
                unsigned so = nb * KBUF_BYTES + (unsigned)(row * ASTR + c4 * 4) * 4;
                CP16(uKst + so, ksrc + (size_t)row * DMODEL + c4 * 4);
                CP16(uVst + so, vsrc + (size_t)row * DMODEL + c4 * 4);
            }
            CP_COMMIT();
        }

        float sf[4][4];
#pragma unroll
        for (int nt = 0; nt < 4; nt++)
#pragma unroll
            for (int j = 0; j < 4; j++) sf[nt][j] = 0.f;
#pragma unroll
        for (int ks = 0; ks < 64; ks += 8) {
            unsigned a[4], bF[4];
            ldsm4(a, uQ + ks * 4);
            ldsm4(bF, uK[0] + cur * KBUF_BYTES + ks * 4);
            mma_tf32(sf[0], a, bF[0], bF[1]);
            mma_tf32(sf[1], a, bF[2], bF[3]);
            ldsm4(bF, uK[1] + cur * KBUF_BYTES + ks * 4);
            mma_tf32(sf[2], a, bF[0], bF[1]);
            mma_tf32(sf[3], a, bF[2], bF[3]);
        }

#pragma unroll
        for (int nt = 0; nt < 4; nt++) {
            int col = nw + nt * 8 + 2 * c;
            float mk0 = msk[kt * 64 + col], mk1 = msk[kt * 64 + col + 1];
            float p0 = __expf(sf[nt][0] + mk0 - rm0) * il0;
            float p1 = __expf(sf[nt][1] + mk1 - rm0) * il0;
            float p2 = __expf(sf[nt][2] + mk0 - rm1) * il1;
            float p3 = __expf(sf[nt][3] + mk1 - rm1) * il1;
            float* wp = wb + (size_t)(mw + r) * SEQ + kt * 64 + col;
            *(float2*)wp = make_float2(p0, p1);
            *(float2*)(wp + 8 * SEQ) = make_float2(p2, p3);
            *(float2*)&Ps[(mw + r) * ASTR + col] =
                make_float2(to_tf32(p0), to_tf32(p1));
            *(float2*)&Ps[(mw + r + 8) * ASTR + col] =
                make_float2(to_tf32(p2), to_tf32(p3));
        }
        __syncthreads();

        const float* Vcur = sh + OFF_V + cur * 4352;
#pragma unroll
        for (int ks = 0; ks < 64; ks += 8) {
            unsigned a[4];
            ldsm4(a, uP + ks * 4);
#pragma unroll
            for (int nt = 0; nt < 4; nt++) {
                unsigned b0 = f2u(Vcur[(ks + c) * ASTR + nw + nt * 8 + r]);
                unsigned b1 = f2u(Vcur[(ks + c + 4) * ASTR + nw + nt * 8 + r]);
                mma_tf32(of[nt], a, b0, b1);
            }
        }
        CP_WAIT0();
        __syncthreads();
    }

    float* ab = g_a + ((size_t)(b * SEQ + q0)) * DMODEL + h * DHEAD;
#pragma unroll
    for (int nt = 0; nt < 4; nt++) {
        int col = nw + nt * 8 + 2 * c;
        *(float2*)(ab + (size_t)(mw + r) * DMODEL + col) =
            make_float2(of[nt][0], of[nt][1]);
        *(float2*)(ab + (size_t)(mw + r + 8) * DMODEL + col) =
            make_float2(of[nt][2], of[nt][3]);
    }
}

// ----------------------------------------------------------------------------
extern "C" void kernel_launch(void* const* d_in, const int* in_sizes, int n_in,
                              void* d_out, int out_size)
{
    const float* Q    = (const float*)d_in[0];
    const float* K    = (const float*)d_in[1];
    const float* V    = (const float*)d_in[2];
    const float* mask = (const float*)d_in[3];
    const float* Wq_w = (const float*)d_in[4];
    const float* Wq_b = (const float*)d_in[5];
    const float* Wk_w = (const float*)d_in[6];
    const float* Wk_b = (const float*)d_in[7];
    const float* Wv_w = (const float*)d_in[8];
    const float* Wv_b = (const float*)d_in[9];
    const float* Wo_w = (const float*)d_in[10];
    const float* Wo_b = (const float*)d_in[11];

    float* out = (float*)d_out;
    float* wts = out + (size_t)BATCH * SEQ * DMODEL;

    float *qb, *kb, *vb, *ab;
    cudaGetSymbolAddress((void**)&qb, g_q);
    cudaGetSymbolAddress((void**)&kb, g_k);
    cudaGetSymbolAddress((void**)&vb, g_v);
    cudaGetSymbolAddress((void**)&ab, g_a);

    const int attn_smem = ATTN_SMEM_FLOATS * 4;
    cudaFuncSetAttribute(attn3,
                         cudaFuncAttributeMaxDynamicSharedMemorySize, attn_smem);

    dim3 gg(512 / 64, (BATCH * SEQ) / 128);
    gemm2<2><<<gg, 256>>>(Q, Wq_w, Wq_b, qb);   // tf32-rounded, pre-scaled 1/8
    gemm2<1><<<gg, 256>>>(K, Wk_w, Wk_b, kb);   // tf32-rounded
    gemm2<1><<<gg, 256>>>(V, Wv_w, Wv_b, vb);   // tf32-rounded

    attn3<<<dim3(SEQ / 64, BATCH * NHEAD), 256, attn_smem>>>(mask, wts);

    gemm2<0><<<gg, 256>>>(ab, Wo_w, Wo_b, out); // plain fp32 out
}

// round 4
// speedup vs baseline: 2.7734x; 1.1785x over previous
#include <cuda_runtime.h>
#include <cstdint>

#define BATCH 4
#define SEQ   2048
#define DMODEL 512
#define NHEAD 8
#define DHEAD 64
#define NKT  (SEQ / 64)  // 32 k-tiles

// Scratch (allocation-free rule: __device__ globals)
__device__ float g_q[(size_t)BATCH * SEQ * DMODEL];
__device__ float g_k[(size_t)BATCH * SEQ * DMODEL];
__device__ float g_v[(size_t)BATCH * SEQ * DMODEL];
__device__ float g_a[(size_t)BATCH * SEQ * DMODEL];

__device__ __forceinline__ float to_tf32(float x) {
    asm("cvt.rna.tf32.f32 %0, %0;" : "+f"(x));
    return x;
}
__device__ __forceinline__ unsigned f2u(float x) { return __float_as_uint(x); }
__device__ __forceinline__ unsigned s2u(const void* p) {
    return (unsigned)__cvta_generic_to_shared(p);
}

__device__ __forceinline__ void mma_tf32(float c[4], const unsigned a[4],
                                         unsigned b0, unsigned b1)
{
    asm volatile(
        "mma.sync.aligned.m16n8k8.row.col.f32.tf32.tf32.f32 "
        "{%0,%1,%2,%3}, {%4,%5,%6,%7}, {%8,%9}, {%0,%1,%2,%3};\n"
        : "+f"(c[0]), "+f"(c[1]), "+f"(c[2]), "+f"(c[3])
        : "r"(a[0]), "r"(a[1]), "r"(a[2]), "r"(a[3]), "r"(b0), "r"(b1));
}

__device__ __forceinline__ void ldsm4(unsigned r[4], unsigned addr) {
    asm volatile("ldmatrix.sync.aligned.m8n8.x4.shared.b16 {%0,%1,%2,%3}, [%4];"
        : "=r"(r[0]), "=r"(r[1]), "=r"(r[2]), "=r"(r[3]) : "r"(addr));
}

#define CP16(dst, src) \
    asm volatile("cp.async.cg.shared.global [%0], [%1], 16;" :: "r"(dst), "l"(src))
#define CP_COMMIT()  asm volatile("cp.async.commit_group;")
#define CP_WAIT0()   asm volatile("cp.async.wait_group 0;" ::: "memory")

// ----------------------------------------------------------------------------
// tf32 GEMM + bias (unchanged from round 3).
// MODE: 0 = plain fp32 out; 1 = tf32-rounded out; 2 = tf32-rounded * 0.125
// ----------------------------------------------------------------------------
template<int MODE>
__global__ void __launch_bounds__(256) gemm2(
    const float* __restrict__ A, const float* __restrict__ W,
    const float* __restrict__ bias, float* __restrict__ C)
{
    __shared__ float As[2][128 * 20];
    __shared__ float Wt[2][64 * 20];

    const int tid = threadIdx.x;
    const int lane = tid & 31, warp = tid >> 5;
    const int mw = (warp >> 1) * 32;
    const int nw = (warp & 1) * 32;
    const int r = lane >> 2, c = lane & 3;

    float acc[2][4][4];
#pragma unroll
    for (int i = 0; i < 2; i++)
#pragma unroll
        for (int j = 0; j < 4; j++)
#pragma unroll
            for (int k = 0; k < 4; k++) acc[i][j][k] = 0.f;

    const float* Ab = A + (size_t)blockIdx.y * 128 * 512;
    const float* Wb = W + blockIdx.x * 64;

    const int arow = tid >> 2, ac4 = tid & 3;
    const int wrow = tid >> 4, wc4 = tid & 15;

    unsigned uA0 = s2u(&As[0][0]) +
        (((mw + (lane & 15)) * 20) + ((lane >> 4) << 2)) * 4;
    unsigned uA1 = uA0 + 16 * 20 * 4;
    unsigned uB0 = s2u(&Wt[0][0]) +
        (((nw + (lane & 7) + ((lane >> 4) << 3)) * 20) + (((lane >> 3) & 1) << 2)) * 4;
    unsigned uB1 = uB0 + 16 * 20 * 4;

    float4 aR0, aR1, wR;
    aR0 = *(const float4*)(Ab + (size_t)arow * 512 + ac4 * 4);
    aR1 = *(const float4*)(Ab + (size_t)(arow + 64) * 512 + ac4 * 4);
    wR  = *(const float4*)(Wb + (size_t)wrow * 512 + wc4 * 4);
    {
        float4 v = aR0;
        v.x = to_tf32(v.x); v.y = to_tf32(v.y); v.z = to_tf32(v.z); v.w = to_tf32(v.w);
        *(float4*)&As[0][arow * 20 + ac4 * 4] = v;
        v = aR1;
        v.x = to_tf32(v.x); v.y = to_tf32(v.y); v.z = to_tf32(v.z); v.w = to_tf32(v.w);
        *(float4*)&As[0][(arow + 64) * 20 + ac4 * 4] = v;
        Wt[0][(wc4 * 4 + 0) * 20 + wrow] = to_tf32(wR.x);
        Wt[0][(wc4 * 4 + 1) * 20 + wrow] = to_tf32(wR.y);
        Wt[0][(wc4 * 4 + 2) * 20 + wrow] = to_tf32(wR.z);
        Wt[0][(wc4 * 4 + 3) * 20 + wrow] = to_tf32(wR.w);
    }
    __syncthreads();

    for (int k0 = 0; k0 < 512; k0 += 16) {
        const int cur = (k0 >> 4) & 1;
        const bool nxt = (k0 + 16) < 512;
        if (nxt) {
            aR0 = *(const float4*)(Ab + (size_t)arow * 512 + k0 + 16 + ac4 * 4);
            aR1 = *(const float4*)(Ab + (size_t)(arow + 64) * 512 + k0 + 16 + ac4 * 4);
            wR  = *(const float4*)(Wb + (size_t)(k0 + 16 + wrow) * 512 + wc4 * 4);
        }
#pragma unroll
        for (int ks = 0; ks < 16; ks += 8) {
            unsigned a0[4], a1[4], bF[4];
            ldsm4(a0, uA0 + cur * 10240 + ks * 4);
            ldsm4(a1, uA1 + cur * 10240 + ks * 4);
            ldsm4(bF, uB0 + cur * 5120 + ks * 4);
            mma_tf32(acc[0][0], a0, bF[0], bF[1]);
            mma_tf32(acc[0][1], a0, bF[2], bF[3]);
            mma_tf32(acc[1][0], a1, bF[0], bF[1]);
            mma_tf32(acc[1][1], a1, bF[2], bF[3]);
            ldsm4(bF, uB1 + cur * 5120 + ks * 4);
            mma_tf32(acc[0][2], a0, bF[0], bF[1]);
            mma_tf32(acc[0][3], a0, bF[2], bF[3]);
            mma_tf32(acc[1][2], a1, bF[0], bF[1]);
            mma_tf32(acc[1][3], a1, bF[2], bF[3]);
        }
        if (nxt) {
            const int nb = cur ^ 1;
            float4 v = aR0;
            v.x = to_tf32(v.x); v.y = to_tf32(v.y); v.z = to_tf32(v.z); v.w = to_tf32(v.w);
            *(float4*)&As[nb][arow * 20 + ac4 * 4] = v;
            v = aR1;
            v.x = to_tf32(v.x); v.y = to_tf32(v.y); v.z = to_tf32(v.z); v.w = to_tf32(v.w);
            *(float4*)&As[nb][(arow + 64) * 20 + ac4 * 4] = v;
            Wt[nb][(wc4 * 4 + 0) * 20 + wrow] = to_tf32(wR.x);
            Wt[nb][(wc4 * 4 + 1) * 20 + wrow] = to_tf32(wR.y);
            Wt[nb][(wc4 * 4 + 2) * 20 + wrow] = to_tf32(wR.z);
            Wt[nb][(wc4 * 4 + 3) * 20 + wrow] = to_tf32(wR.w);
        }
        __syncthreads();
    }

#pragma unroll
    for (int mt = 0; mt < 2; mt++)
#pragma unroll
    for (int nt = 0; nt < 4; nt++) {
        int col = blockIdx.x * 64 + nw + nt * 8 + 2 * c;
        float bx = __ldg(bias + col), by = __ldg(bias + col + 1);
        size_t row0 = blockIdx.y * 128 + mw + mt * 16 + r;
        float v0 = acc[mt][nt][0] + bx, v1 = acc[mt][nt][1] + by;
        float v2 = acc[mt][nt][2] + bx, v3 = acc[mt][nt][3] + by;
        if (MODE == 2) { v0 *= 0.125f; v1 *= 0.125f; v2 *= 0.125f; v3 *= 0.125f; }
        if (MODE >= 1) {
            v0 = to_tf32(v0); v1 = to_tf32(v1); v2 = to_tf32(v2); v3 = to_tf32(v3);
        }
        *(float2*)(C + row0 * 512 + col) = make_float2(v0, v1);
        *(float2*)(C + (row0 + 8) * 512 + col) = make_float2(v2, v3);
    }
}

// ----------------------------------------------------------------------------
// Flash attention v4: register softmax stats, shfl-built P fragments,
// conflict-free V loads, 1 barrier per k-tile.
// 8 warps: warp = (mw-group 0..3, nwi 0..1). Warp S-tile 16x32.
// PV: warp covers its 32 keys x all 64 dims; pair-combined at the end.
// Smem floats: Q[64*68] K[2*64*68] V[2*64*72] msk[2048] stats[256]
// ----------------------------------------------------------------------------
#define QSTR 68
#define VSTR 72
#define OFF_K   4352
#define OFF_V   13056
#define OFF_MSK 22272
#define OFF_ST  24320
#define ATTN_SMEM_FLOATS 24576
#define KBUF_BYTES (4352 * 4)

__global__ void __launch_bounds__(256, 2) attn4(
    const float* __restrict__ mask, float* __restrict__ wts)
{
    extern __shared__ float sh[];
    float* msk = sh + OFF_MSK;
    float2* stats = (float2*)(sh + OFF_ST);   // [row][nwi]

    const int tid = threadIdx.x;
    const int lane = tid & 31, warp = tid >> 5;
    const int mw = (warp >> 1) * 16;
    const int nwi = warp & 1;
    const int nw = nwi * 32;
    const int r = lane >> 2, c = lane & 3;

    const int qt = blockIdx.x, bh = blockIdx.y;
    const int b = bh >> 3, h = bh & 7;
    const int q0 = qt * 64;

    const float* qg = g_q + ((size_t)(b * SEQ + q0)) * DMODEL + h * DHEAD;
    const float* kg = g_k + (size_t)b * SEQ * DMODEL + h * DHEAD;
    const float* vg = g_v + (size_t)b * SEQ * DMODEL + h * DHEAD;

    const unsigned uQst = s2u(sh);
    const unsigned uKst = s2u(sh + OFF_K);
    const unsigned uVst = s2u(sh + OFF_V);

    // prologue: Q + K0
#pragma unroll
    for (int i = 0; i < 4; i++) {
        int f = tid + 256 * i;
        int row = f >> 4, c4 = f & 15;
        CP16(uQst + (unsigned)(row * QSTR + c4 * 4) * 4,
             qg + (size_t)row * DMODEL + c4 * 4);
        CP16(uKst + (unsigned)(row * QSTR + c4 * 4) * 4,
             kg + (size_t)row * DMODEL + c4 * 4);
    }
    CP_COMMIT();
#pragma unroll
    for (int j = 0; j < 2; j++) {
        int idx = tid + 256 * j;
        float4 mv = *(const float4*)(mask + (size_t)b * SEQ + idx * 4);
        msk[idx * 4 + 0] = mv.x * -1e9f;
        msk[idx * 4 + 1] = mv.y * -1e9f;
        msk[idx * 4 + 2] = mv.z * -1e9f;
        msk[idx * 4 + 3] = mv.w * -1e9f;
    }
    CP_WAIT0();
    __syncthreads();

    // fragment base addresses
    const unsigned uQ = uQst +
        (((mw + (lane & 15)) * QSTR) + ((lane >> 4) << 2)) * 4;
    unsigned uK[2];
#pragma unroll
    for (int ntp = 0; ntp < 2; ntp++)
        uK[ntp] = uKst +
            (((nw + ntp * 16 + (lane & 7) + ((lane >> 4) << 3)) * QSTR) +
             (((lane >> 3) & 1) << 2)) * 4;

    // register softmax stats (per warp-half, rows R0 = mw+r, R1 = mw+r+8)
    float m0 = -1e30f, l0 = 0.f, m1 = -1e30f, l1 = 0.f;

    // ======================= Pass A: stats =======================
#pragma unroll 1
    for (int kt = 0; kt < NKT; ++kt) {
        const int cur = kt & 1;
        if (kt + 1 < NKT) {
            const int nb = (kt + 1) & 1;
            const float* src = kg + (size_t)(kt + 1) * 64 * DMODEL;
#pragma unroll
            for (int i = 0; i < 4; i++) {
                int f = tid + 256 * i;
                int row = f >> 4, c4 = f & 15;
                CP16(uKst + nb * KBUF_BYTES + (unsigned)(row * QSTR + c4 * 4) * 4,
                     src + (size_t)row * DMODEL + c4 * 4);
            }
            CP_COMMIT();
        }

        float sf[4][4];
#pragma unroll
        for (int nt = 0; nt < 4; nt++)
#pragma unroll
            for (int j = 0; j < 4; j++) sf[nt][j] = 0.f;

#pragma unroll
        for (int ks = 0; ks < 64; ks += 8) {
            unsigned a[4], bF[4];
            ldsm4(a, uQ + ks * 4);
            ldsm4(bF, uK[0] + cur * KBUF_BYTES + ks * 4);
            mma_tf32(sf[0], a, bF[0], bF[1]);
            mma_tf32(sf[1], a, bF[2], bF[3]);
            ldsm4(bF, uK[1] + cur * KBUF_BYTES + ks * 4);
            mma_tf32(sf[2], a, bF[0], bF[1]);
            mma_tf32(sf[3], a, bF[2], bF[3]);
        }

        float mx0 = -1e30f, mx1 = -1e30f;
#pragma unroll
        for (int nt = 0; nt < 4; nt++) {
            int col = kt * 64 + nw + nt * 8 + 2 * c;
            float mk0 = msk[col], mk1 = msk[col + 1];
            sf[nt][0] += mk0; sf[nt][1] += mk1;
            sf[nt][2] += mk0; sf[nt][3] += mk1;
            mx0 = fmaxf(mx0, fmaxf(sf[nt][0], sf[nt][1]));
            mx1 = fmaxf(mx1, fmaxf(sf[nt][2], sf[nt][3]));
        }
        mx0 = fmaxf(mx0, __shfl_xor_sync(0xffffffffu, mx0, 1));
        mx0 = fmaxf(mx0, __shfl_xor_sync(0xffffffffu, mx0, 2));
        mx1 = fmaxf(mx1, __shfl_xor_sync(0xffffffffu, mx1, 1));
        mx1 = fmaxf(mx1, __shfl_xor_sync(0xffffffffu, mx1, 2));
        float s0 = 0.f, s1 = 0.f;
#pragma unroll
        for (int nt = 0; nt < 4; nt++) {
            s0 += __expf(sf[nt][0] - mx0) + __expf(sf[nt][1] - mx0);
            s1 += __expf(sf[nt][2] - mx1) + __expf(sf[nt][3] - mx1);
        }
        s0 += __shfl_xor_sync(0xffffffffu, s0, 1);
        s0 += __shfl_xor_sync(0xffffffffu, s0, 2);
        s1 += __shfl_xor_sync(0xffffffffu, s1, 1);
        s1 += __shfl_xor_sync(0xffffffffu, s1, 2);

        float nm0 = fmaxf(m0, mx0);
        l0 = l0 * __expf(m0 - nm0) + s0 * __expf(mx0 - nm0); m0 = nm0;
        float nm1 = fmaxf(m1, mx1);
        l1 = l1 * __expf(m1 - nm1) + s1 * __expf(mx1 - nm1); m1 = nm1;

        CP_WAIT0();
        __syncthreads();
    }

    // combine warp-pair stats (once)
    if (c == 0) {
        stats[(mw + r) * 2 + nwi] = make_float2(m0, l0);
        stats[(mw + r + 8) * 2 + nwi] = make_float2(m1, l1);
    }
    __syncthreads();
    float rm0, il0, rm1, il1;
    {
        float2 aS = stats[(mw + r) * 2], bS = stats[(mw + r) * 2 + 1];
        rm0 = fmaxf(aS.x, bS.x);
        il0 = 1.f / (aS.y * __expf(aS.x - rm0) + bS.y * __expf(bS.x - rm0));
        float2 cS = stats[(mw + r + 8) * 2], dS = stats[(mw + r + 8) * 2 + 1];
        rm1 = fmaxf(cS.x, dS.x);
        il1 = 1.f / (cS.y * __expf(cS.x - rm1) + dS.y * __expf(dS.x - rm1));
    }

    // pass-B prologue: K0 + V0
#pragma unroll
    for (int i = 0; i < 4; i++) {
        int f = tid + 256 * i;
        int row = f >> 4, c4 = f & 15;
        CP16(uKst + (unsigned)(row * QSTR + c4 * 4) * 4,
             kg + (size_t)row * DMODEL + c4 * 4);
        CP16(uVst + (unsigned)(row * VSTR + c4 * 4) * 4,
             vg + (size_t)row * DMODEL + c4 * 4);
    }
    CP_COMMIT();
    CP_WAIT0();
    __syncthreads();

    // ======================= Pass B: weights + PV =======================
    float of[8][4];
#pragma unroll
    for (int nt8 = 0; nt8 < 8; nt8++)
#pragma unroll
        for (int j = 0; j < 4; j++) of[nt8][j] = 0.f;

    float* wb = wts + ((size_t)bh * SEQ + q0) * SEQ;

#pragma unroll 1
    for (int kt = 0; kt < NKT; ++kt) {
        const int cur = kt & 1;
        if (kt + 1 < NKT) {
            const int nb = (kt + 1) & 1;
            const float* ksrc = kg + (size_t)(kt + 1) * 64 * DMODEL;
            const float* vsrc = vg + (size_t)(kt + 1) * 64 * DMODEL;
#pragma unroll
            for (int i = 0; i < 4; i++) {
                int f = tid + 256 * i;
                int row = f >> 4, c4 = f & 15;
                CP16(uKst + nb * KBUF_BYTES + (unsigned)(row * QSTR + c4 * 4) * 4,
                     ksrc + (size_t)row * DMODEL + c4 * 4);
                CP16(uVst + nb * (VSTR * 64 * 4) + (unsigned)(row * VSTR + c4 * 4) * 4,
                     vsrc + (size_t)row * DMODEL + c4 * 4);
            }
            CP_COMMIT();
        }

        // recompute S
        float sf[4][4];
#pragma unroll
        for (int nt = 0; nt < 4; nt++)
#pragma unroll
            for (int j = 0; j < 4; j++) sf[nt][j] = 0.f;
#pragma unroll
        for (int ks = 0; ks < 64; ks += 8) {
            unsigned a[4], bF[4];
            ldsm4(a, uQ + ks * 4);
            ldsm4(bF, uK[0] + cur * KBUF_BYTES + ks * 4);
            mma_tf32(sf[0], a, bF[0], bF[1]);
            mma_tf32(sf[1], a, bF[2], bF[3]);
            ldsm4(bF, uK[1] + cur * KBUF_BYTES + ks * 4);
            mma_tf32(sf[2], a, bF[0], bF[1]);
            mma_tf32(sf[3], a, bF[2], bF[3]);
        }

        // p = softmax weight; write global; keep tf32-rounded p in sf
#pragma unroll
        for (int nt = 0; nt < 4; nt++) {
            int col = nw + nt * 8 + 2 * c;
            float mk0 = msk[kt * 64 + col], mk1 = msk[kt * 64 + col + 1];
            float p0 = __expf(sf[nt][0] + mk0 - rm0) * il0;
            float p1 = __expf(sf[nt][1] + mk1 - rm0) * il0;
            float p2 = __expf(sf[nt][2] + mk0 - rm1) * il1;
            float p3 = __expf(sf[nt][3] + mk1 - rm1) * il1;
            float* wp = wb + (size_t)(mw + r) * SEQ + kt * 64 + col;
            *(float2*)wp = make_float2(p0, p1);
            *(float2*)(wp + 8 * SEQ) = make_float2(p2, p3);
            sf[nt][0] = to_tf32(p0); sf[nt][1] = to_tf32(p1);
            sf[nt][2] = to_tf32(p2); sf[nt][3] = to_tf32(p3);
        }

        // PV over this warp's 32 keys, all 64 dims; A-frags via quad shfl
        const float* Vcur = sh + OFF_V + cur * (VSTR * 64);
        const int src0 = (lane & ~3) | (c >> 1);
        const int src1 = src0 + 2;
#pragma unroll
        for (int kb = 0; kb < 4; kb++) {
            unsigned a[4];
            {
                float g0 = __shfl_sync(0xffffffffu, sf[kb][0], src0);
                float g1 = __shfl_sync(0xffffffffu, sf[kb][1], src0);
                a[0] = f2u((c & 1) ? g1 : g0);
                float g2 = __shfl_sync(0xffffffffu, sf[kb][2], src0);
                float g3 = __shfl_sync(0xffffffffu, sf[kb][3], src0);
                a[1] = f2u((c & 1) ? g3 : g2);
                float h0 = __shfl_sync(0xffffffffu, sf[kb][0], src1);
                float h1 = __shfl_sync(0xffffffffu, sf[kb][1], src1);
                a[2] = f2u((c & 1) ? h1 : h0);
                float h2 = __shfl_sync(0xffffffffu, sf[kb][2], src1);
                float h3 = __shfl_sync(0xffffffffu, sf[kb][3], src1);
                a[3] = f2u((c & 1) ? h3 : h2);
            }
            const float* Vr = Vcur + (nw + kb * 8 + c) * VSTR;
#pragma unroll
            for (int nt8 = 0; nt8 < 8; nt8++) {
                unsigned b0 = f2u(Vr[nt8 * 8 + r]);
                unsigned b1 = f2u(Vr[4 * VSTR + nt8 * 8 + r]);
                mma_tf32(of[nt8], a, b0, b1);
            }
        }

        CP_WAIT0();
        __syncthreads();
    }

    // combine warp pairs' O partials (staging reuses Q area)
    float* stg = sh + (warp >> 1) * 1024;   // [16 rows][64 dims]
    if (nwi == 1) {
#pragma unroll
        for (int nt8 = 0; nt8 < 8; nt8++) {
            *(float2*)&stg[r * 64 + nt8 * 8 + 2 * c] =
                make_float2(of[nt8][0], of[nt8][1]);
            *(float2*)&stg[(r + 8) * 64 + nt8 * 8 + 2 * c] =
                make_float2(of[nt8][2], of[nt8][3]);
        }
    }
    __syncthreads();
    if (nwi == 0) {
        float* ab = g_a + ((size_t)(b * SEQ + q0 + mw + r)) * DMODEL + h * DHEAD;
#pragma unroll
        for (int nt8 = 0; nt8 < 8; nt8++) {
            float2 s0 = *(float2*)&stg[r * 64 + nt8 * 8 + 2 * c];
            float2 s1 = *(float2*)&stg[(r + 8) * 64 + nt8 * 8 + 2 * c];
            *(float2*)(ab + nt8 * 8 + 2 * c) =
                make_float2(of[nt8][0] + s0.x, of[nt8][1] + s0.y);
            *(float2*)(ab + (size_t)8 * DMODEL + nt8 * 8 + 2 * c) =
                make_float2(of[nt8][2] + s1.x, of[nt8][3] + s1.y);
        }
    }
}

// ----------------------------------------------------------------------------
extern "C" void kernel_launch(void* const* d_in, const int* in_sizes, int n_in,
                              void* d_out, int out_size)
{
    const float* Q    = (const float*)d_in[0];
    const float* K    = (const float*)d_in[1];
    const float* V    = (const float*)d_in[2];
    const float* mask = (const float*)d_in[3];
    const float* Wq_w = (const float*)d_in[4];
    const float* Wq_b = (const float*)d_in[5];
    const float* Wk_w = (const float*)d_in[6];
    const float* Wk_b = (const float*)d_in[7];
    const float* Wv_w = (const float*)d_in[8];
    const float* Wv_b = (const float*)d_in[9];
    const float* Wo_w = (const float*)d_in[10];
    const float* Wo_b = (const float*)d_in[11];

    float* out = (float*)d_out;
    float* wts = out + (size_t)BATCH * SEQ * DMODEL;

    float *qb, *kb, *vb, *ab;
    cudaGetSymbolAddress((void**)&qb, g_q);
    cudaGetSymbolAddress((void**)&kb, g_k);
    cudaGetSymbolAddress((void**)&vb, g_v);
    cudaGetSymbolAddress((void**)&ab, g_a);

    const int attn_smem = ATTN_SMEM_FLOATS * 4;
    cudaFuncSetAttribute(attn4,
                         cudaFuncAttributeMaxDynamicSharedMemorySize, attn_smem);

    dim3 gg(512 / 64, (BATCH * SEQ) / 128);
    gemm2<2><<<gg, 256>>>(Q, Wq_w, Wq_b, qb);   // tf32-rounded, pre-scaled 1/8
    gemm2<1><<<gg, 256>>>(K, Wk_w, Wk_b, kb);   // tf32-rounded
    gemm2<1><<<gg, 256>>>(V, Wv_w, Wv_b, vb);   // tf32-rounded

    attn4<<<dim3(SEQ / 64, BATCH * NHEAD), 256, attn_smem>>>(mask, wts);

    gemm2<0><<<gg, 256>>>(ab, Wo_w, Wo_b, out); // plain fp32 out
}